// round 14
// baseline (speedup 1.0000x reference)
#include <cuda_runtime.h>
#include <math.h>
#include <stdint.h>

// XSReLU_cw_perc_param: out = relu(x - thr[b,c]),
//   thr = s[k_lo] + (s[k_hi] - s[k_lo]) * sigmoid(plogit[c]),
//   s = sorted row (4096 elems), k_lo/k_hi from sigmoid(plogit[0]) +/- 0.02.
// Dual radix select, 11/11/10 bits, packed 16|16 dual histogram, survivor masks.

#define ROW_LEN 4096
#define THREADS 256
#define PER_THR 16
#define NB      2048          // bins in pass A/B (11 bits); pass C uses 1024 of them

__device__ __forceinline__ unsigned f2s(float f) {
    unsigned u = __float_as_uint(f);
    return (u & 0x80000000u) ? ~u : (u | 0x80000000u);
}
__device__ __forceinline__ float s2f(unsigned u) {
    u = (u & 0x80000000u) ? (u ^ 0x80000000u) : ~u;
    return __uint_as_float(u);
}

// Packed dual scan+select over NB bins (8 consecutive bins per thread).
// hist fields: lo count = bits[0:16), hi count = bits[16:32).
// On return (after a barrier): sel[0]=binLo, sel[1]=residualLo, sel[2]=binHi, sel[3]=residualHi.
__device__ __forceinline__ void pscan_select(const unsigned* __restrict__ hist,
                                             unsigned* warp_sums, unsigned* sel,
                                             int tid, int lane, int wid,
                                             unsigned rLo, unsigned rHi)
{
    unsigned hb[8];
    unsigned local = 0;
    #pragma unroll
    for (int b = 0; b < 8; ++b) { hb[b] = hist[8 * tid + b]; local += hb[b]; }

    unsigned inc = local;                       // packed scan; fields never overflow (<=4096)
    #pragma unroll
    for (int s = 1; s < 32; s <<= 1) {
        unsigned n = __shfl_up_sync(0xffffffffu, inc, s);
        if (lane >= s) inc += n;
    }
    if (lane == 31) warp_sums[wid] = inc;
    __syncthreads();
    unsigned off = 0;
    #pragma unroll
    for (int w = 0; w < 8; ++w)
        if (w < wid) off += warp_sums[w];
    unsigned excl = off + inc - local;
    unsigned exLo = excl & 0xFFFFu, exHi = excl >> 16;
    #pragma unroll
    for (int b = 0; b < 8; ++b) {
        unsigned hLo = hb[b] & 0xFFFFu, hHi = hb[b] >> 16;
        if (rLo - exLo < hLo) { sel[0] = 8u * tid + b; sel[1] = rLo - exLo; }  // unsigned wrap trick
        if (rHi - exHi < hHi) { sel[2] = 8u * tid + b; sel[3] = rHi - exHi; }
        exLo += hLo; exHi += hHi;
    }
    __syncthreads();
}

__global__ void __launch_bounds__(THREADS, 6)
XSReLU_cw_perc_param_47528108097997_kernel(const float* __restrict__ x,
                                           const float* __restrict__ plogit,
                                           float* __restrict__ out, int C) {
    __shared__ unsigned hist[NB];
    __shared__ unsigned warp_sums[8];
    __shared__ unsigned sel[4];

    const int row  = blockIdx.x;
    const int tid  = threadIdx.x;
    const int lane = tid & 31;
    const int wid  = tid >> 5;

    const float4* __restrict__ xr =
        reinterpret_cast<const float4*>(x) + (size_t)row * (ROW_LEN / 4);
    float4* __restrict__ orow =
        reinterpret_cast<float4*>(out) + (size_t)row * (ROW_LEN / 4);

    // ---- load row (coalesced float4) -> order-preserving uint keys (floats recomputed later)
    unsigned u[PER_THR];
    #pragma unroll
    for (int j = 0; j < 4; ++j) {
        float4 t = xr[tid + j * THREADS];
        u[4 * j + 0] = f2s(t.x);
        u[4 * j + 1] = f2s(t.y);
        u[4 * j + 2] = f2s(t.z);
        u[4 * j + 3] = f2s(t.w);
    }

    // ---- clear histogram
    #pragma unroll
    for (int b = 0; b < 8; ++b) hist[tid + THREADS * b] = 0;

    // ---- ranks (f32 arithmetic + trunc cast to match jnp)
    const float p0 = 1.0f / (1.0f + expf(-plogit[0]));
    int kLoI = min(max((int)(4096.0f * (p0 - 0.02f)), 0), ROW_LEN - 1);
    int kHiI = min(max((int)(4096.0f * (p0 + 0.02f)), 0), ROW_LEN - 1);
    __syncthreads();

    // ================= pass A: bits[31:21], ungated, packed dual count ========
    #pragma unroll
    for (int j = 0; j < PER_THR; ++j)
        atomicAdd(&hist[u[j] >> 21], 0x10001u);
    __syncthreads();
    pscan_select(hist, warp_sums, sel, tid, lane, wid, (unsigned)kLoI, (unsigned)kHiI);
    const unsigned binALo = sel[0], binAHi = sel[2];
    unsigned rLo = sel[1], rHi = sel[3];
    #pragma unroll
    for (int b = 0; b < 8; ++b) hist[tid + THREADS * b] = 0;
    __syncthreads();

    // ================= pass B: bits[20:10], gated on pass-A bin; build mask ===
    unsigned mAny = 0;
    #pragma unroll
    for (int j = 0; j < PER_THR; ++j) {
        unsigned dA  = u[j] >> 21;
        unsigned add = 0;
        if (dA == binALo) add = 1u;
        if (dA == binAHi) add += 0x10000u;
        if (add) { mAny |= 1u << j; atomicAdd(&hist[(u[j] >> 10) & 0x7FFu], add); }
    }
    __syncthreads();
    pscan_select(hist, warp_sums, sel, tid, lane, wid, rLo, rHi);
    const unsigned pref22Lo = (binALo << 11) | sel[0];
    const unsigned pref22Hi = (binAHi << 11) | sel[2];
    rLo = sel[1]; rHi = sel[3];
    #pragma unroll
    for (int b = 0; b < 8; ++b) hist[tid + THREADS * b] = 0;
    __syncthreads();

    // ================= pass C: bits[9:0], gated on survivor mask ==============
    #pragma unroll
    for (int j = 0; j < PER_THR; ++j) {
        if ((mAny >> j) & 1u) {
            unsigned h22 = u[j] >> 10;
            unsigned add = 0;
            if (h22 == pref22Lo) add = 1u;
            if (h22 == pref22Hi) add += 0x10000u;
            if (add) atomicAdd(&hist[u[j] & 0x3FFu], add);
        }
    }
    __syncthreads();
    pscan_select(hist, warp_sums, sel, tid, lane, wid, rLo, rHi);

    // ---- threshold + fused epilogue (floats recomputed bit-exactly from keys)
    const float xl  = s2f((pref22Lo << 10) | sel[0]);
    const float xh  = s2f((pref22Hi << 10) | sel[2]);
    const float pc  = 1.0f / (1.0f + expf(-plogit[row % C]));
    const float thr = xl + (xh - xl) * pc;

    #pragma unroll
    for (int j = 0; j < 4; ++j) {
        float4 t;
        t.x = fmaxf(s2f(u[4 * j + 0]) - thr, 0.0f);
        t.y = fmaxf(s2f(u[4 * j + 1]) - thr, 0.0f);
        t.z = fmaxf(s2f(u[4 * j + 2]) - thr, 0.0f);
        t.w = fmaxf(s2f(u[4 * j + 3]) - thr, 0.0f);
        orow[tid + j * THREADS] = t;
    }
}

extern "C" void kernel_launch(void* const* d_in, const int* in_sizes, int n_in,
                              void* d_out, int out_size) {
    const float* x      = (const float*)d_in[0];   // [B, C, H, W] f32
    const float* plogit = (const float*)d_in[1];   // [C] f32
    float*       out    = (float*)d_out;

    const int total = in_sizes[0];                 // B*C*H*W
    const int C     = in_sizes[1];                 // 256
    const int rows  = total / ROW_LEN;             // B*C

    XSReLU_cw_perc_param_47528108097997_kernel<<<rows, THREADS>>>(x, plogit, out, C);
}

// round 15
// speedup vs baseline: 1.2876x; 1.2876x over previous
#include <cuda_runtime.h>
#include <math.h>
#include <stdint.h>

// XSReLU_cw_perc_param: out = relu(x - thr[b,c]),
//   thr = s[k_lo] + (s[k_hi] - s[k_lo]) * sigmoid(plogit[c]),
//   s = sorted row (4096 elems), k_lo/k_hi from sigmoid(plogit[0]) +/- 0.02.
// Dual radix select, 4 x 8-bit passes, packed 16|16 dual histograms,
// warp-0-only scan/select, survivor-mask gating, one row per 256-thread CTA.

#define ROW_LEN 4096
#define THREADS 256
#define PER_THR 16

__device__ __forceinline__ unsigned f2s(float f) {
    unsigned u = __float_as_uint(f);
    return u ^ ((unsigned)(((int)u) >> 31) | 0x80000000u);
}
__device__ __forceinline__ float s2f(unsigned u) {
    unsigned m = (~(unsigned)(((int)u) >> 31)) | 0x80000000u;
    return __uint_as_float(u ^ m);
}

// Packed dual scan + select over 256 bins, executed by warp 0 only.
// hist fields: lo count = bits[0:16), hi count = bits[16:32).
// After return: sel[0]=binLo, sel[1]=residLo, sel[2]=binHi, sel[3]=residHi.
__device__ __forceinline__ void pscan(const unsigned* __restrict__ h_,
                                      unsigned* sel, int tid,
                                      unsigned rLo, unsigned rHi) {
    if (tid < 32) {
        const uint4* hv = reinterpret_cast<const uint4*>(h_);
        uint4 a = hv[2 * tid], c = hv[2 * tid + 1];
        unsigned hb[8] = {a.x, a.y, a.z, a.w, c.x, c.y, c.z, c.w};
        unsigned local = 0;
        #pragma unroll
        for (int i = 0; i < 8; ++i) local += hb[i];
        unsigned inc = local;                     // packed scan, fields <= 4096
        #pragma unroll
        for (int s = 1; s < 32; s <<= 1) {
            unsigned n = __shfl_up_sync(0xffffffffu, inc, s);
            if (tid >= s) inc += n;
        }
        unsigned excl = inc - local;
        unsigned exLo = excl & 0xFFFFu, exHi = excl >> 16;
        #pragma unroll
        for (int b = 0; b < 8; ++b) {
            unsigned hLo = hb[b] & 0xFFFFu, hHi = hb[b] >> 16;
            if (rLo - exLo < hLo) { sel[0] = 8u * tid + b; sel[1] = rLo - exLo; }
            if (rHi - exHi < hHi) { sel[2] = 8u * tid + b; sel[3] = rHi - exHi; }
            exLo += hLo; exHi += hHi;
        }
    }
    __syncthreads();
}

__global__ void __launch_bounds__(THREADS, 6)
XSReLU_cw_perc_param_47528108097997_kernel(const float* __restrict__ x,
                                           const float* __restrict__ plogit,
                                           float* __restrict__ out, int C) {
    __shared__ __align__(16) unsigned h0[256];
    __shared__ __align__(16) unsigned h1[256];
    __shared__ __align__(16) unsigned h2[256];
    __shared__ __align__(16) unsigned h3[256];
    __shared__ unsigned sel[4];

    const int row  = blockIdx.x;
    const int tid  = threadIdx.x;
    const int lane = tid & 31;
    const unsigned lmlt = (1u << lane) - 1u;   // lanemask_lt

    const float4* __restrict__ xr =
        reinterpret_cast<const float4*>(x) + (size_t)row * (ROW_LEN / 4);
    float4* __restrict__ orow =
        reinterpret_cast<float4*>(out) + (size_t)row * (ROW_LEN / 4);

    // ---- load row (coalesced float4) -> order-preserving uint keys
    unsigned u[PER_THR];
    #pragma unroll
    for (int j = 0; j < 4; ++j) {
        float4 t = xr[tid + j * THREADS];
        u[4 * j + 0] = f2s(t.x);
        u[4 * j + 1] = f2s(t.y);
        u[4 * j + 2] = f2s(t.z);
        u[4 * j + 3] = f2s(t.w);
    }

    // ---- clear all four histograms once
    h0[tid] = 0; h1[tid] = 0; h2[tid] = 0; h3[tid] = 0;

    // ---- ranks (f32 arithmetic + trunc cast to match jnp)
    const float p0 = 1.0f / (1.0f + expf(-plogit[0]));
    const unsigned rLo0 =
        (unsigned)min(max((int)(4096.0f * (p0 - 0.02f)), 0), ROW_LEN - 1);
    const unsigned rHi0 =
        (unsigned)min(max((int)(4096.0f * (p0 + 0.02f)), 0), ROW_LEN - 1);
    __syncthreads();

    // ========== pass 0: byte3, warp-aggregated packed atomics ==========
    #pragma unroll
    for (int j = 0; j < PER_THR; ++j) {
        unsigned d = u[j] >> 24;
        unsigned m = __match_any_sync(0xffffffffu, d);
        if ((m & lmlt) == 0)                       // lowest lane in group
            atomicAdd(&h0[d], (unsigned)__popc(m) * 0x10001u);
    }
    __syncthreads();
    pscan(h0, sel, tid, rLo0, rHi0);
    const unsigned bLo = sel[0], bHi = sel[2];
    unsigned rLo = sel[1], rHi = sel[3];

    // ========== pass 1: byte2, gated on byte3; build survivor mask ==========
    unsigned m1 = 0;
    #pragma unroll
    for (int j = 0; j < PER_THR; ++j) {
        unsigned b0  = u[j] >> 24;
        unsigned add = (b0 == bLo) + ((b0 == bHi) << 16);
        if (add) { m1 |= 1u << j; atomicAdd(&h1[(u[j] >> 16) & 0xFFu], add); }
    }
    __syncthreads();
    pscan(h1, sel, tid, rLo, rHi);
    unsigned pLo = (bLo << 8) | sel[0];
    unsigned pHi = (bHi << 8) | sel[2];
    rLo = sel[1]; rHi = sel[3];

    // ========== pass 2: byte1, gated on survivor mask + 16-bit prefix ==========
    unsigned m2 = 0;
    #pragma unroll
    for (int j = 0; j < PER_THR; ++j) {
        if (m1 & (1u << j)) {
            unsigned t   = u[j] >> 16;
            unsigned add = (t == pLo) + ((t == pHi) << 16);
            if (add) { m2 |= 1u << j; atomicAdd(&h2[(u[j] >> 8) & 0xFFu], add); }
        }
    }
    __syncthreads();
    pscan(h2, sel, tid, rLo, rHi);
    pLo = (pLo << 8) | sel[0];
    pHi = (pHi << 8) | sel[2];
    rLo = sel[1]; rHi = sel[3];

    // ========== pass 3: byte0, gated on survivor mask + 24-bit prefix ==========
    #pragma unroll
    for (int j = 0; j < PER_THR; ++j) {
        if (m2 & (1u << j)) {
            unsigned t   = u[j] >> 8;
            unsigned add = (t == pLo) + ((t == pHi) << 16);
            if (add) atomicAdd(&h3[u[j] & 0xFFu], add);
        }
    }
    __syncthreads();
    pscan(h3, sel, tid, rLo, rHi);

    // ---- threshold + fused epilogue (floats recomputed bit-exactly)
    const float xl = s2f((pLo << 8) | sel[0]);
    const float xh = s2f((pHi << 8) | sel[2]);
    const int   c  = ((C & (C - 1)) == 0) ? (row & (C - 1)) : (row % C);
    const float pc = 1.0f / (1.0f + expf(-plogit[c]));
    const float thr = xl + (xh - xl) * pc;

    #pragma unroll
    for (int j = 0; j < 4; ++j) {
        float4 t;
        t.x = fmaxf(s2f(u[4 * j + 0]) - thr, 0.0f);
        t.y = fmaxf(s2f(u[4 * j + 1]) - thr, 0.0f);
        t.z = fmaxf(s2f(u[4 * j + 2]) - thr, 0.0f);
        t.w = fmaxf(s2f(u[4 * j + 3]) - thr, 0.0f);
        orow[tid + j * THREADS] = t;
    }
}

extern "C" void kernel_launch(void* const* d_in, const int* in_sizes, int n_in,
                              void* d_out, int out_size) {
    const float* x      = (const float*)d_in[0];   // [B, C, H, W] f32
    const float* plogit = (const float*)d_in[1];   // [C] f32
    float*       out    = (float*)d_out;

    const int total = in_sizes[0];                 // B*C*H*W
    const int C     = in_sizes[1];                 // 256
    const int rows  = total / ROW_LEN;             // B*C

    XSReLU_cw_perc_param_47528108097997_kernel<<<rows, THREADS>>>(x, plogit, out, C);
}